// round 7
// baseline (speedup 1.0000x reference)
#include <cuda_runtime.h>
#include <cstdint>

// Embedding gather via TMA bulk-copy pipeline.
// out[t, :] = weights[ids[t], :]
// ids: 16384 int32, weights: [50257,1024] fp32 (4KB rows), out: [16384,1024] fp32.
//
// Each 32-thread CTA copies TOK_PER_CTA rows through a STAGES-deep smem ring:
//   cp.async.bulk g->s (mbarrier complete_tx), then cp.async.bulk s->g
//   (bulk_group; wait_group.read gates buffer reuse).
// All issue from one elected thread: zero register pressure for in-flight data,
// 16KB outstanding per CTA, ~13 CTAs/SM -> latency fully hidden, LTS-cap bound.

static constexpr int ROW_BYTES   = 4096;  // 1024 fp32
static constexpr int STAGES      = 4;
static constexpr int TOK_PER_CTA = 8;

__device__ __forceinline__ void mbar_init(uint32_t addr) {
    asm volatile("mbarrier.init.shared::cta.b64 [%0], 1;" :: "r"(addr));
}
__device__ __forceinline__ void mbar_expect_tx(uint32_t addr, uint32_t bytes) {
    asm volatile("mbarrier.arrive.expect_tx.shared::cta.b64 _, [%0], %1;"
                 :: "r"(addr), "r"(bytes) : "memory");
}
__device__ __forceinline__ void mbar_wait(uint32_t addr, uint32_t parity) {
    asm volatile(
        "{\n\t"
        ".reg .pred P;\n\t"
        "WAIT_%=:\n\t"
        "mbarrier.try_wait.parity.shared::cta.b64 P, [%0], %1, 0x989680;\n\t"
        "@P bra.uni DONE_%=;\n\t"
        "bra.uni WAIT_%=;\n\t"
        "DONE_%=:\n\t"
        "}"
        :: "r"(addr), "r"(parity) : "memory");
}
__device__ __forceinline__ void bulk_g2s(uint32_t dst_smem, const void* src,
                                         uint32_t bytes, uint32_t mbar) {
    asm volatile(
        "cp.async.bulk.shared::cta.global.mbarrier::complete_tx::bytes "
        "[%0], [%1], %2, [%3];"
        :: "r"(dst_smem), "l"(src), "r"(bytes), "r"(mbar) : "memory");
}
__device__ __forceinline__ void bulk_s2g(void* dst, uint32_t src_smem, uint32_t bytes) {
    asm volatile(
        "cp.async.bulk.global.shared::cta.bulk_group [%0], [%1], %2;"
        :: "l"(dst), "r"(src_smem), "r"(bytes) : "memory");
}
__device__ __forceinline__ void bulk_commit() {
    asm volatile("cp.async.bulk.commit_group;" ::: "memory");
}
__device__ __forceinline__ void bulk_wait_read0() {
    asm volatile("cp.async.bulk.wait_group.read 0;" ::: "memory");
}
__device__ __forceinline__ void bulk_wait_all() {
    asm volatile("cp.async.bulk.wait_group 0;" ::: "memory");
}

__global__ void __launch_bounds__(32) embed_tma_kernel(
    const int* __restrict__ ids,
    const char* __restrict__ w,
    char* __restrict__ out,
    int n_tokens)
{
    __shared__ alignas(128) char buf[STAGES][ROW_BYTES];
    __shared__ alignas(8)  uint64_t mbar[STAGES];

    if (threadIdx.x != 0) return;   // single driver thread per CTA

    const int base = blockIdx.x * TOK_PER_CTA;
    int nt = n_tokens - base;
    if (nt <= 0) return;
    if (nt > TOK_PER_CTA) nt = TOK_PER_CTA;

    uint32_t buf_s[STAGES], mbar_s[STAGES];
    #pragma unroll
    for (int s = 0; s < STAGES; ++s) {
        buf_s[s]  = (uint32_t)__cvta_generic_to_shared(&buf[s][0]);
        mbar_s[s] = (uint32_t)__cvta_generic_to_shared(&mbar[s]);
        mbar_init(mbar_s[s]);
    }
    // make mbarrier init visible to the async proxy
    asm volatile("fence.proxy.async.shared::cta;" ::: "memory");

    // prologue: fill the pipeline with loads
    #pragma unroll
    for (int j = 0; j < STAGES; ++j) {
        if (j < nt) {
            int row = __ldg(ids + base + j);
            mbar_expect_tx(mbar_s[j], ROW_BYTES);
            bulk_g2s(buf_s[j], w + (size_t)row * ROW_BYTES, ROW_BYTES, mbar_s[j]);
        }
    }

    uint32_t phase = 0;   // bit s = current parity of stage s
    for (int i = 0; i < nt; ++i) {
        const int s = i & (STAGES - 1);
        // wait for load of token i
        mbar_wait(mbar_s[s], (phase >> s) & 1u);
        phase ^= (1u << s);
        // stream row out
        bulk_s2g(out + (size_t)(base + i) * ROW_BYTES, buf_s[s], ROW_BYTES);
        bulk_commit();
        // refill this stage with token i+STAGES (after our store has read the buffer)
        const int nxt = i + STAGES;
        if (nxt < nt) {
            bulk_wait_read0();   // all committed stores have finished reading smem
            int row = __ldg(ids + base + nxt);
            mbar_expect_tx(mbar_s[s], ROW_BYTES);
            bulk_g2s(buf_s[s], w + (size_t)row * ROW_BYTES, ROW_BYTES, mbar_s[s]);
        }
    }
    // ensure all stores fully complete before kernel exit
    bulk_wait_all();
}

extern "C" void kernel_launch(void* const* d_in, const int* in_sizes, int n_in,
                              void* d_out, int out_size)
{
    const int*  ids = (const int*)d_in[0];
    const char* w   = (const char*)d_in[1];
    char*       out = (char*)d_out;

    int n_tokens = in_sizes[0];                                   // 16384
    int blocks   = (n_tokens + TOK_PER_CTA - 1) / TOK_PER_CTA;    // 2048
    embed_tma_kernel<<<blocks, 32>>>(ids, w, out, n_tokens);
}